// round 14
// baseline (speedup 1.0000x reference)
#include <cuda_runtime.h>
#include <cuda_fp16.h>
#include <cstdint>

#define T_LEN 16384
#define BATCH 4
#define CRES 128
#define NBLK 40
#define SKIPLEN 4096
#define SKIPSTART (T_LEN - SKIPLEN)

#define THREADS 256
#define TT 64

// SMEM layout (bytes) — XOR-swizzled, zero padding
#define SM_XD  0            // 64 rows x 256B fp16 (Xd, later G)
#define SM_XC  16384        // 64 rows x 256B fp16 (Xc); third W buffer in tail
#define SM_W0  32768        // 16KB K-chunk buffer 0 (128 rows x 128B)
#define SM_W1  49152        // 16KB K-chunk buffer 1
#define SM_TOTAL 65536

// ---------------- device scratch ----------------
__device__ float g_actA[(size_t)BATCH * T_LEN * CRES];
__device__ float g_actB[(size_t)BATCH * T_LEN * CRES];
__device__ __align__(16) __half g_mirA[(size_t)BATCH * T_LEN * CRES];
__device__ __align__(16) __half g_mirB[(size_t)BATCH * T_LEN * CRES];
// per block: 5 matrices x 2 K-chunks x 8192 fp16 (16KB).
// chunk index = m*2 + c;  m: 0=wd tap0, 1=wd tap1, 2=wres, 3=wskA, 4=wskB
__device__ __align__(16) __half g_wimg[(size_t)NBLK * 10 * 8192];

// ---------------- helpers ----------------
__device__ __forceinline__ uint32_t smem_u32(const void* p) {
    uint32_t a;
    asm("{ .reg .u64 t; cvta.to.shared.u64 t, %1; cvt.u32.u64 %0, t; }" : "=r"(a) : "l"(p));
    return a;
}
__device__ __forceinline__ void ldsm4(uint32_t* r, uint32_t addr) {
    asm volatile("ldmatrix.sync.aligned.m8n8.x4.shared.b16 {%0,%1,%2,%3}, [%4];"
                 : "=r"(r[0]), "=r"(r[1]), "=r"(r[2]), "=r"(r[3]) : "r"(addr));
}
__device__ __forceinline__ void mma16816(float* d, const uint32_t* a, const uint32_t* b) {
    asm volatile("mma.sync.aligned.m16n8k16.row.col.f32.f16.f16.f32 "
                 "{%0,%1,%2,%3},{%4,%5,%6,%7},{%8,%9},{%0,%1,%2,%3};"
                 : "+f"(d[0]), "+f"(d[1]), "+f"(d[2]), "+f"(d[3])
                 : "r"(a[0]), "r"(a[1]), "r"(a[2]), "r"(a[3]), "r"(b[0]), "r"(b[1]));
}
__device__ __forceinline__ void cpa16(uint32_t dst, const void* src) {
    asm volatile("cp.async.cg.shared.global [%0], [%1], 16;" :: "r"(dst), "l"(src));
}
__device__ __forceinline__ void cpa16z(uint32_t dst, const void* src, uint32_t n) {
    asm volatile("cp.async.cg.shared.global [%0], [%1], 16, %2;"
                 :: "r"(dst), "l"(src), "r"(n));
}
#define CP_COMMIT()  asm volatile("cp.async.commit_group;" ::: "memory")
#define CP_WAITG(n)  asm volatile("cp.async.wait_group %0;" :: "n"(n) : "memory")

__device__ __forceinline__ uint32_t pack_h2(float x0, float x1) {
    __half2 h = __floats2half2_rn(x0, x1);
    return *reinterpret_cast<uint32_t*>(&h);
}
__device__ __forceinline__ float gate_fn(float h) {
    h = fminf(fmaxf(h, -30.f), 30.f);
    float e = __expf(-h);
    float e2 = e * e;
    return __fdividef(1.f - e2, (1.f + e2) * (1.f + e));
}

// ---------------- pre-pass kernels ----------------
__global__ void transpose_x(const float* __restrict__ x, float* __restrict__ xt,
                            __half* __restrict__ xh) {
    __shared__ float tile[32][33];
    int b = blockIdx.z, c0 = blockIdx.y * 32, t0 = blockIdx.x * 32;
    int lx = threadIdx.x, ly = threadIdx.y;
    #pragma unroll
    for (int i = 0; i < 32; i += 8)
        tile[ly + i][lx] = x[((size_t)b * CRES + c0 + ly + i) * T_LEN + t0 + lx];
    __syncthreads();
    #pragma unroll
    for (int i = 0; i < 32; i += 8) {
        float v = tile[lx][ly + i];
        size_t idx = ((size_t)b * T_LEN + t0 + ly + i) * CRES + c0 + lx;
        xt[idx] = v;
        xh[idx] = __float2half_rn(v);
    }
}

__global__ void prep_weights(const float* __restrict__ wd, const float* __restrict__ wr,
                             const float* __restrict__ wsk, __half* __restrict__ img) {
    int blk = blockIdx.x, m = blockIdx.y;
    for (int e = threadIdx.x; e < 16384; e += 256) {
        int o = e >> 7, k = e & 127;
        float v;
        if      (m == 0) v = wd[((size_t)blk * 16384 + o * 128 + k) * 2 + 0];
        else if (m == 1) v = wd[((size_t)blk * 16384 + o * 128 + k) * 2 + 1];
        else if (m == 2) v = wr[(size_t)blk * 16384 + o * 128 + k];
        else if (m == 3) v = wsk[(size_t)blk * 32768 + o * 128 + k];
        else             v = wsk[(size_t)blk * 32768 + (o + 128) * 128 + k];
        int c = k >> 6, kl = k & 63;
        size_t base = (size_t)blk * 81920 + (size_t)(m * 2 + c) * 8192;
        img[base + o * 64 + kl] = __float2half_rn(v);
    }
}

// ---------------- main block kernel ----------------
__global__ void __launch_bounds__(THREADS, 3)
wnet_mma(const float* __restrict__ in, const __half* __restrict__ mirin,
         float* __restrict__ resout, __half* __restrict__ mirout,
         const __half* __restrict__ img, float* __restrict__ skipout, int dil)
{
    extern __shared__ char smem[];
    const uint32_t sb = smem_u32(smem);
    const int tid = threadIdx.x;
    const int lane = tid & 31, wid = tid >> 5;
    const int wm = wid & 1;        // 2 M groups (32 t rows each)
    const int wn = wid >> 1;       // 4 N groups (32 out cols each)
    // interleaved heavy/light: heavy (orig bx>=192) mapped to every 4th launch index
    const int li = blockIdx.x;
    const int bx = ((li & 3) == 0) ? (192 + (li >> 2))
                                   : ((li >> 2) * 3 + (li & 3) - 1);
    const int b = blockIdx.y, t0 = bx * TT;
    const bool skip = (t0 >= SKIPSTART);

    // A-side ldmatrix constants (256B rows, 16 chunks)
    const uint32_t arow = (uint32_t)(wm * 32 + (lane & 15)) * 256;
    const uint32_t rxa  = (uint32_t)(lane & 7) << 4;
    const uint32_t kla  = (uint32_t)(lane >> 4) << 4;
    // B-side ldmatrix constants (128B rows, 8 chunks)
    const uint32_t brow = (uint32_t)(wn * 32 + (lane & 7) + ((lane >> 4) << 3)) * 128;
    const uint32_t rxb  = (uint32_t)(lane & 7) << 4;
    const uint32_t klb  = (uint32_t)((lane >> 3) & 1) << 4;

    const float*  src  = in    + (size_t)b * T_LEN * CRES;
    const __half* msrc = mirin + (size_t)b * T_LEN * CRES;

    // ---- 16KB K-chunk load (128 rows x 128B, swizzled) ----
    auto load_img = [&](int cidx, uint32_t wslot) {
        const char* g = (const char*)(img + (size_t)cidx * 8192);
        #pragma unroll
        for (int i = 0; i < 4; ++i) {
            uint32_t e = (uint32_t)tid + i * THREADS;      // 0..1023 16B chunks
            uint32_t row = e >> 3, k = e & 7;
            cpa16(sb + wslot + row * 128 + ((k ^ (row & 7)) << 4), g + (size_t)e * 16);
        }
        CP_COMMIT();
    };

    // ---- activation tile: cp.async fp16 mirror -> swizzled SMEM (zero-fill t<0) ----
    auto loadA = [&](uint32_t slot, bool shifted) {
        #pragma unroll
        for (int i = 0; i < 4; ++i) {
            uint32_t e = (uint32_t)tid + i * THREADS;      // 0..1023 16B chunks
            uint32_t row = e >> 4, k = e & 15;
            int ts = shifted ? (t0 + (int)row - dil) : (t0 + (int)row);
            const char* s = (const char*)(msrc + (size_t)(ts < 0 ? 0 : ts) * CRES) + k * 16;
            uint32_t dst = sb + slot + row * 256 + ((k ^ (row & 7)) << 4);
            cpa16z(dst, s, ts >= 0 ? 16u : 0u);
        }
        CP_COMMIT();
    };

    float acc[2][4][4];
    auto zero_acc = [&]() {
        #pragma unroll
        for (int mt = 0; mt < 2; ++mt)
            #pragma unroll
            for (int nt = 0; nt < 4; ++nt)
                #pragma unroll
                for (int j = 0; j < 4; ++j) acc[mt][nt][j] = 0.f;
    };

    // ---- one K-chunk GEMM (K=64, warp tile 32x32) ----
    auto gemm_chunk = [&](uint32_t aSlot, uint32_t wslot, int k0base) {
        #pragma unroll
        for (int k0l = 0; k0l < 4; ++k0l) {
            uint32_t aoffs = ((((uint32_t)(k0base + k0l)) * 32 + kla) ^ rxa);
            uint32_t boffs = (((uint32_t)k0l * 32 + klb) ^ rxb);
            uint32_t a[2][4], bb[2][4];
            ldsm4(a[0], sb + aSlot + arow + aoffs);
            ldsm4(a[1], sb + aSlot + arow + 4096 + aoffs);
            ldsm4(bb[0], sb + wslot + brow + boffs);
            ldsm4(bb[1], sb + wslot + brow + 2048 + boffs);
            #pragma unroll
            for (int mt = 0; mt < 2; ++mt)
                #pragma unroll
                for (int nt = 0; nt < 4; ++nt)
                    mma16816(acc[mt][nt], a[mt], &bb[nt >> 1][(nt & 1) * 2]);
        }
    };

    // ---- direct skip store: acc -> skipout[o][t], 32B segments ----
    auto store_skip = [&](int half) {
        float* sd = skipout + ((size_t)b * 256 + half * 128) * SKIPLEN + (t0 - SKIPSTART);
        #pragma unroll
        for (int mt = 0; mt < 2; ++mt)
            #pragma unroll
            for (int nt = 0; nt < 4; ++nt) {
                int c = wn * 32 + nt * 8 + (lane & 3) * 2;
                #pragma unroll
                for (int h = 0; h < 2; ++h) {
                    int r = wm * 32 + mt * 16 + (lane >> 2) + h * 8;
                    sd[(size_t)c * SKIPLEN + r]       = acc[mt][nt][h * 2 + 0];
                    sd[(size_t)(c + 1) * SKIPLEN + r] = acc[mt][nt][h * 2 + 1];
                }
            }
    };

    // ================= prologue =================
    loadA(SM_XD, true);                  // g: Xd (shifted)
    loadA(SM_XC, false);                 // g: Xc
    load_img(0, SM_W0);                  // g: wd0 c0
    load_img(1, SM_W1);                  // g: wd0 c1
    CP_WAITG(1);                         // XD, XC, chunk0 ready (chunk1 may lag)
    __syncthreads();

    // ---- phase 1: h = Wd0 @ Xd + Wd1 @ Xc ----
    zero_acc();
    gemm_chunk(SM_XD, SM_W0, 0);         // wd0 c0
    CP_WAITG(0); __syncthreads(); load_img(2, SM_W0);
    gemm_chunk(SM_XD, SM_W1, 4);         // wd0 c1
    CP_WAITG(0); __syncthreads(); load_img(3, SM_W1);
    gemm_chunk(SM_XC, SM_W0, 0);         // wd1 c0
    CP_WAITG(0); __syncthreads(); load_img(4, SM_W0);
    gemm_chunk(SM_XC, SM_W1, 4);         // wd1 c1
    CP_WAITG(0); __syncthreads();        // chunk4 (wres c0) resident; W1 & XC free

    // prefetch wres c1 and (if heavy) wskA c0 into the freed XC slot
    load_img(5, SM_W1);
    if (skip) load_img(6, SM_XC);

    // ---- gate -> G into XD slot ----
    #pragma unroll
    for (int mt = 0; mt < 2; ++mt)
        #pragma unroll
        for (int nt = 0; nt < 4; ++nt) {
            int c = wn * 32 + nt * 8 + (lane & 3) * 2;
            #pragma unroll
            for (int h = 0; h < 2; ++h) {
                int r = wm * 32 + mt * 16 + (lane >> 2) + h * 8;
                float g0 = gate_fn(acc[mt][nt][h * 2 + 0]);
                float g1 = gate_fn(acc[mt][nt][h * 2 + 1]);
                uint32_t off = (uint32_t)r * 256
                             + (uint32_t)((((c >> 3) ^ (r & 7)) << 4) + (c & 7) * 2);
                *(uint32_t*)(smem + SM_XD + off) = pack_h2(g0, g1);
            }
        }
    zero_acc();
    __syncthreads();                     // G visible to all warps

    // ---- phase 2: res = Wres @ G ----
    gemm_chunk(SM_XD, SM_W0, 0);         // wres c0
    if (skip) { CP_WAITG(1); } else { CP_WAITG(0); }   // chunk5 complete
    __syncthreads();                     // W0 consumers done
    if (skip) load_img(7, SM_W0);        // wskA c1
    gemm_chunk(SM_XD, SM_W1, 4);         // wres c1

    // ---- residual epilogue: out = acc + Xc(global fp32); also fp16 mirror ----
    // (overlaps the in-flight chunk 6/7 loads for heavy CTAs)
    {
        float*  dst  = resout + ((size_t)b * T_LEN + t0) * CRES;
        __half* mdst = mirout + ((size_t)b * T_LEN + t0) * CRES;
        const float* xc = src + (size_t)t0 * CRES;
        #pragma unroll
        for (int mt = 0; mt < 2; ++mt)
            #pragma unroll
            for (int nt = 0; nt < 4; ++nt) {
                int c = wn * 32 + nt * 8 + (lane & 3) * 2;
                #pragma unroll
                for (int h = 0; h < 2; ++h) {
                    int r = wm * 32 + mt * 16 + (lane >> 2) + h * 8;
                    float2 x = *(const float2*)(xc + (size_t)r * CRES + c);
                    float2 o;
                    o.x = acc[mt][nt][h * 2 + 0] + x.x;
                    o.y = acc[mt][nt][h * 2 + 1] + x.y;
                    *(float2*)(dst + (size_t)r * CRES + c) = o;
                    *(uint32_t*)(mdst + (size_t)r * CRES + c) = pack_h2(o.x, o.y);
                }
            }
    }
    if (!skip) return;

    // ================= skip phase (chunks 6..9; buffers XC, W0, W1, XC) =================
    CP_WAITG(1); __syncthreads();        // chunk6 (XC) ready; W1 consumers done
    load_img(8, SM_W1);                  // wskB c0
    zero_acc();
    gemm_chunk(SM_XD, SM_XC, 0);         // wskA c0 (weights in XC slot)
    CP_WAITG(1); __syncthreads();        // chunk7 (W0) ready; XC consumers done
    load_img(9, SM_XC);                  // wskB c1 -> XC
    gemm_chunk(SM_XD, SM_W0, 4);         // wskA c1
    store_skip(0);
    CP_WAITG(1); __syncthreads();        // chunk8 (W1) ready
    zero_acc();
    gemm_chunk(SM_XD, SM_W1, 0);         // wskB c0
    CP_WAITG(0); __syncthreads();        // chunk9 (XC) ready
    gemm_chunk(SM_XD, SM_XC, 4);         // wskB c1
    store_skip(1);
}

// ---------------- host ----------------
extern "C" void kernel_launch(void* const* d_in, const int* in_sizes, int n_in,
                              void* d_out, int out_size)
{
    const float* x      = (const float*)d_in[0];
    const float* w_dil  = (const float*)d_in[1];
    const float* w_res  = (const float*)d_in[2];
    const float* w_skip = (const float*)d_in[3];
    float* out = (float*)d_out;

    float *pA, *pB;
    __half *pMA, *pMB, *pimg;
    cudaGetSymbolAddress((void**)&pA, g_actA);
    cudaGetSymbolAddress((void**)&pB, g_actB);
    cudaGetSymbolAddress((void**)&pMA, g_mirA);
    cudaGetSymbolAddress((void**)&pMB, g_mirB);
    cudaGetSymbolAddress((void**)&pimg, g_wimg);

    cudaFuncSetAttribute(wnet_mma, cudaFuncAttributeMaxDynamicSharedMemorySize, SM_TOTAL);

    transpose_x<<<dim3(T_LEN / 32, CRES / 32, BATCH), dim3(32, 8)>>>(x, pA, pMA);
    prep_weights<<<dim3(NBLK, 5), 256>>>(w_dil, w_res, w_skip, pimg);

    for (int i = 0; i < NBLK; ++i) {
        const float*  srcp = (i & 1) ? pB : pA;
        float*        dstp = (i & 1) ? pA : pB;
        const __half* msrc = (i & 1) ? pMB : pMA;
        __half*       mdst = (i & 1) ? pMA : pMB;
        wnet_mma<<<dim3(T_LEN / TT, BATCH), THREADS, SM_TOTAL>>>(
            srcp, msrc, dstp, mdst,
            pimg + (size_t)i * 81920,
            out + (size_t)i * BATCH * 256 * SKIPLEN,
            1 << (i % 10));
    }
}

// round 15
// speedup vs baseline: 1.0422x; 1.0422x over previous
#include <cuda_runtime.h>
#include <cuda_fp16.h>
#include <cstdint>

#define T_LEN 16384
#define BATCH 4
#define CRES 128
#define NBLK 40
#define SKIPLEN 4096
#define SKIPSTART (T_LEN - SKIPLEN)

#define THREADS 256
#define TT 64

// SMEM layout (bytes) — XOR-swizzled, zero padding
#define SM_XD  0            // 64 rows x 256B fp16 (Xd, later G)
#define SM_XC  16384        // 64 rows x 256B fp16 (Xc)
#define SM_W   32768        // 4 pairs x 2 buffers x 4KB slices
#define SM_TOTAL 65536

// ---------------- device scratch ----------------
__device__ float g_actA[(size_t)BATCH * T_LEN * CRES];
__device__ float g_actB[(size_t)BATCH * T_LEN * CRES];
__device__ __align__(16) __half g_mirA[(size_t)BATCH * T_LEN * CRES];
__device__ __align__(16) __half g_mirB[(size_t)BATCH * T_LEN * CRES];
// per block: 10 chunks of 8192 fp16 (16KB), chunk = m*2+c (K=64 halves):
// m: 0=wd tap0, 1=wd tap1, 2=wres, 3=wskA, 4=wskB
__device__ __align__(16) __half g_wimg[(size_t)NBLK * 10 * 8192];

// ---------------- helpers ----------------
__device__ __forceinline__ uint32_t smem_u32(const void* p) {
    uint32_t a;
    asm("{ .reg .u64 t; cvta.to.shared.u64 t, %1; cvt.u32.u64 %0, t; }" : "=r"(a) : "l"(p));
    return a;
}
__device__ __forceinline__ void ldsm4(uint32_t* r, uint32_t addr) {
    asm volatile("ldmatrix.sync.aligned.m8n8.x4.shared.b16 {%0,%1,%2,%3}, [%4];"
                 : "=r"(r[0]), "=r"(r[1]), "=r"(r[2]), "=r"(r[3]) : "r"(addr));
}
__device__ __forceinline__ void mma16816(float* d, const uint32_t* a, const uint32_t* b) {
    asm volatile("mma.sync.aligned.m16n8k16.row.col.f32.f16.f16.f32 "
                 "{%0,%1,%2,%3},{%4,%5,%6,%7},{%8,%9},{%0,%1,%2,%3};"
                 : "+f"(d[0]), "+f"(d[1]), "+f"(d[2]), "+f"(d[3])
                 : "r"(a[0]), "r"(a[1]), "r"(a[2]), "r"(a[3]), "r"(b[0]), "r"(b[1]));
}
__device__ __forceinline__ void cpa16(uint32_t dst, const void* src) {
    asm volatile("cp.async.cg.shared.global [%0], [%1], 16;" :: "r"(dst), "l"(src));
}
__device__ __forceinline__ void cpa16z(uint32_t dst, const void* src, uint32_t n) {
    asm volatile("cp.async.cg.shared.global [%0], [%1], 16, %2;"
                 :: "r"(dst), "l"(src), "r"(n));
}
#define CP_COMMIT()  asm volatile("cp.async.commit_group;" ::: "memory")
#define CP_WAITG(n)  asm volatile("cp.async.wait_group %0;" :: "n"(n) : "memory")

__device__ __forceinline__ uint32_t pack_h2(float x0, float x1) {
    __half2 h = __floats2half2_rn(x0, x1);
    return *reinterpret_cast<uint32_t*>(&h);
}
__device__ __forceinline__ float gate_fn(float h) {
    h = fminf(fmaxf(h, -30.f), 30.f);
    float e = __expf(-h);
    float e2 = e * e;
    return __fdividef(1.f - e2, (1.f + e2) * (1.f + e));
}

// ---------------- pre-pass kernels ----------------
__global__ void transpose_x(const float* __restrict__ x, float* __restrict__ xt,
                            __half* __restrict__ xh) {
    __shared__ float tile[32][33];
    int b = blockIdx.z, c0 = blockIdx.y * 32, t0 = blockIdx.x * 32;
    int lx = threadIdx.x, ly = threadIdx.y;
    #pragma unroll
    for (int i = 0; i < 32; i += 8)
        tile[ly + i][lx] = x[((size_t)b * CRES + c0 + ly + i) * T_LEN + t0 + lx];
    __syncthreads();
    #pragma unroll
    for (int i = 0; i < 32; i += 8) {
        float v = tile[lx][ly + i];
        size_t idx = ((size_t)b * T_LEN + t0 + ly + i) * CRES + c0 + lx;
        xt[idx] = v;
        xh[idx] = __float2half_rn(v);
    }
}

__global__ void prep_weights(const float* __restrict__ wd, const float* __restrict__ wr,
                             const float* __restrict__ wsk, __half* __restrict__ img) {
    int blk = blockIdx.x, m = blockIdx.y;
    for (int e = threadIdx.x; e < 16384; e += 256) {
        int o = e >> 7, k = e & 127;
        float v;
        if      (m == 0) v = wd[((size_t)blk * 16384 + o * 128 + k) * 2 + 0];
        else if (m == 1) v = wd[((size_t)blk * 16384 + o * 128 + k) * 2 + 1];
        else if (m == 2) v = wr[(size_t)blk * 16384 + o * 128 + k];
        else if (m == 3) v = wsk[(size_t)blk * 32768 + o * 128 + k];
        else             v = wsk[(size_t)blk * 32768 + (o + 128) * 128 + k];
        int c = k >> 6, kl = k & 63;
        size_t base = (size_t)blk * 81920 + (size_t)(m * 2 + c) * 8192;
        img[base + o * 64 + kl] = __float2half_rn(v);
    }
}

// ---------------- main block kernel ----------------
__global__ void __launch_bounds__(THREADS, 3)
wnet_mma(const float* __restrict__ in, const __half* __restrict__ mirin,
         float* __restrict__ resout, __half* __restrict__ mirout,
         const __half* __restrict__ img, float* __restrict__ skipout, int dil)
{
    extern __shared__ char smem[];
    const uint32_t sb = smem_u32(smem);
    const int tid = threadIdx.x;
    const int lane = tid & 31, wid = tid >> 5;
    const int wm = wid & 1;        // 2 M groups (32 t rows each)
    const int wn = wid >> 1;       // 4 N groups (32 out cols each); pair id
    // heavy-first remap (R12-proven): skip CTAs launch first
    const int bx = (blockIdx.x + 192) & 255;
    const int b = blockIdx.y, t0 = bx * TT;
    const bool skip = (t0 >= SKIPSTART);
    const int lim = skip ? 10 : 6;

    // A-side ldmatrix constants (256B rows, 16 chunks)
    const uint32_t arow = (uint32_t)(wm * 32 + (lane & 15)) * 256;
    const uint32_t rxa  = (uint32_t)(lane & 7) << 4;
    const uint32_t kla  = (uint32_t)(lane >> 4) << 4;
    // B-side: pair-private slice, 32 rows x 128B
    const uint32_t pairbase = SM_W + (uint32_t)wn * 8192;
    const uint32_t browL = (uint32_t)((lane & 7) + ((lane >> 4) << 3)) * 128;
    const uint32_t rxb   = (uint32_t)(lane & 7) << 4;
    const uint32_t klb   = (uint32_t)((lane >> 3) & 1) << 4;

    const float*  src  = in    + (size_t)b * T_LEN * CRES;
    const __half* msrc = mirin + (size_t)b * T_LEN * CRES;

    #define PAIR_BAR() asm volatile("bar.sync %0, 64;" :: "r"(wn + 1) : "memory")

    // ---- pair-slice weight load: 4KB (32 o-rows x 64 k), wm==0 warp only ----
    auto load_slice = [&](int cj) {
        const char* g = (const char*)(img + (size_t)cj * 8192 + (size_t)wn * 2048);
        uint32_t wb = sb + pairbase + ((uint32_t)(cj & 1) << 12);
        #pragma unroll
        for (int i = 0; i < 8; ++i) {
            uint32_t e = (uint32_t)lane + i * 32;          // 0..255 16B chunks
            uint32_t row = e >> 3, j = e & 7;
            cpa16(wb + row * 128 + ((j ^ (row & 7)) << 4), g + (size_t)e * 16);
        }
        CP_COMMIT();
    };

    // ---- activation tiles: cp.async fp16 mirror -> swizzled SMEM (one group) ----
    auto loadA_both = [&]() {
        #pragma unroll
        for (int s = 0; s < 2; ++s) {
            uint32_t slot = s ? SM_XC : SM_XD;
            #pragma unroll
            for (int i = 0; i < 4; ++i) {
                uint32_t e = (uint32_t)tid + i * THREADS;
                uint32_t row = e >> 4, k = e & 15;
                int ts = s ? (t0 + (int)row) : (t0 + (int)row - dil);
                const char* sp = (const char*)(msrc + (size_t)(ts < 0 ? 0 : ts) * CRES) + k * 16;
                uint32_t dst = sb + slot + row * 256 + ((k ^ (row & 7)) << 4);
                cpa16z(dst, sp, ts >= 0 ? 16u : 0u);
            }
        }
        CP_COMMIT();
    };

    float acc[2][4][4];
    auto zero_acc = [&]() {
        #pragma unroll
        for (int mt = 0; mt < 2; ++mt)
            #pragma unroll
            for (int nt = 0; nt < 4; ++nt)
                #pragma unroll
                for (int j = 0; j < 4; ++j) acc[mt][nt][j] = 0.f;
    };

    // ---- one K=64 chunk GEMM on the pair slice ----
    auto gemm_chunk = [&](uint32_t aSlot, int cj) {
        uint32_t wb = sb + pairbase + ((uint32_t)(cj & 1) << 12);
        int k0base = (cj & 1) * 4;
        #pragma unroll
        for (int k0l = 0; k0l < 4; ++k0l) {
            uint32_t aoffs = ((((uint32_t)(k0base + k0l)) * 32 + kla) ^ rxa);
            uint32_t boffs = (((uint32_t)k0l * 32 + klb) ^ rxb);
            uint32_t a[2][4], bb[2][4];
            ldsm4(a[0], sb + aSlot + arow + aoffs);
            ldsm4(a[1], sb + aSlot + arow + 4096 + aoffs);
            ldsm4(bb[0], wb + browL + boffs);
            ldsm4(bb[1], wb + browL + 2048 + boffs);
            #pragma unroll
            for (int mt = 0; mt < 2; ++mt)
                #pragma unroll
                for (int nt = 0; nt < 4; ++nt)
                    mma16816(acc[mt][nt], a[mt], &bb[nt >> 1][(nt & 1) * 2]);
        }
    };

    // ---- pair-pipelined step ----
    auto step = [&](int cj, uint32_t aSlot) {
        if (cj > 0) PAIR_BAR();                        // pair done chunk cj-1
        if (wm == 0) {
            if (cj == 0)            { CP_WAITG(1); }
            else if (cj + 1 < lim)  { load_slice(cj + 1); CP_WAITG(1); }
            else                    { CP_WAITG(0); }
        }
        PAIR_BAR();                                    // slice cj visible to pair
        gemm_chunk(aSlot, cj);
    };

    // ---- direct skip store: acc -> skipout[o][t], 32B segments ----
    auto store_skip = [&](int half) {
        float* sd = skipout + ((size_t)b * 256 + half * 128) * SKIPLEN + (t0 - SKIPSTART);
        #pragma unroll
        for (int mt = 0; mt < 2; ++mt)
            #pragma unroll
            for (int nt = 0; nt < 4; ++nt) {
                int c = wn * 32 + nt * 8 + (lane & 3) * 2;
                #pragma unroll
                for (int h = 0; h < 2; ++h) {
                    int r = wm * 32 + mt * 16 + (lane >> 2) + h * 8;
                    sd[(size_t)c * SKIPLEN + r]       = acc[mt][nt][h * 2 + 0];
                    sd[(size_t)(c + 1) * SKIPLEN + r] = acc[mt][nt][h * 2 + 1];
                }
            }
    };

    // ================= prologue =================
    loadA_both();                        // group A (all threads)
    if (wm == 0) { load_slice(0); load_slice(1); }   // groups w0, w1 (wm=0 only)
    if (wm == 0) { CP_WAITG(2); } else { CP_WAITG(0); }   // own A group done
    __syncthreads();                     // XD, XC visible CTA-wide

    // ---- phase 1: h = Wd0 @ Xd + Wd1 @ Xc (chunks 0-3) ----
    zero_acc();
    step(0, SM_XD); step(1, SM_XD);
    step(2, SM_XC); step(3, SM_XC);
    __syncthreads();                     // all pairs done reading XD (and phase 1)

    // ---- gate -> G into XD slot ----
    #pragma unroll
    for (int mt = 0; mt < 2; ++mt)
        #pragma unroll
        for (int nt = 0; nt < 4; ++nt) {
            int c = wn * 32 + nt * 8 + (lane & 3) * 2;
            #pragma unroll
            for (int h = 0; h < 2; ++h) {
                int r = wm * 32 + mt * 16 + (lane >> 2) + h * 8;
                float g0 = gate_fn(acc[mt][nt][h * 2 + 0]);
                float g1 = gate_fn(acc[mt][nt][h * 2 + 1]);
                uint32_t off = (uint32_t)r * 256
                             + (uint32_t)((((c >> 3) ^ (r & 7)) << 4) + (c & 7) * 2);
                *(uint32_t*)(smem + SM_XD + off) = pack_h2(g0, g1);
            }
        }
    zero_acc();
    __syncthreads();                     // G visible CTA-wide

    // ---- phase 2: res = Wres @ G (chunks 4-5) ----
    step(4, SM_XD); step(5, SM_XD);

    // ---- residual epilogue: out = acc + Xc(global fp32); also fp16 mirror ----
    {
        float*  dst  = resout + ((size_t)b * T_LEN + t0) * CRES;
        __half* mdst = mirout + ((size_t)b * T_LEN + t0) * CRES;
        const float* xc = src + (size_t)t0 * CRES;
        #pragma unroll
        for (int mt = 0; mt < 2; ++mt)
            #pragma unroll
            for (int nt = 0; nt < 4; ++nt) {
                int c = wn * 32 + nt * 8 + (lane & 3) * 2;
                #pragma unroll
                for (int h = 0; h < 2; ++h) {
                    int r = wm * 32 + mt * 16 + (lane >> 2) + h * 8;
                    float2 x = *(const float2*)(xc + (size_t)r * CRES + c);
                    float2 o;
                    o.x = acc[mt][nt][h * 2 + 0] + x.x;
                    o.y = acc[mt][nt][h * 2 + 1] + x.y;
                    *(float2*)(dst + (size_t)r * CRES + c) = o;
                    *(uint32_t*)(mdst + (size_t)r * CRES + c) = pack_h2(o.x, o.y);
                }
            }
    }
    if (!skip) return;

    // ================= skip phase (chunks 6-9, G unchanged) =================
    zero_acc();
    step(6, SM_XD); step(7, SM_XD);
    store_skip(0);
    zero_acc();
    step(8, SM_XD); step(9, SM_XD);
    store_skip(1);
}

// ---------------- host ----------------
extern "C" void kernel_launch(void* const* d_in, const int* in_sizes, int n_in,
                              void* d_out, int out_size)
{
    const float* x      = (const float*)d_in[0];
    const float* w_dil  = (const float*)d_in[1];
    const float* w_res  = (const float*)d_in[2];
    const float* w_skip = (const float*)d_in[3];
    float* out = (float*)d_out;

    float *pA, *pB;
    __half *pMA, *pMB, *pimg;
    cudaGetSymbolAddress((void**)&pA, g_actA);
    cudaGetSymbolAddress((void**)&pB, g_actB);
    cudaGetSymbolAddress((void**)&pMA, g_mirA);
    cudaGetSymbolAddress((void**)&pMB, g_mirB);
    cudaGetSymbolAddress((void**)&pimg, g_wimg);

    cudaFuncSetAttribute(wnet_mma, cudaFuncAttributeMaxDynamicSharedMemorySize, SM_TOTAL);

    transpose_x<<<dim3(T_LEN / 32, CRES / 32, BATCH), dim3(32, 8)>>>(x, pA, pMA);
    prep_weights<<<dim3(NBLK, 5), 256>>>(w_dil, w_res, w_skip, pimg);

    for (int i = 0; i < NBLK; ++i) {
        const float*  srcp = (i & 1) ? pB : pA;
        float*        dstp = (i & 1) ? pA : pB;
        const __half* msrc = (i & 1) ? pMB : pMA;
        __half*       mdst = (i & 1) ? pMA : pMB;
        wnet_mma<<<dim3(T_LEN / TT, BATCH), THREADS, SM_TOTAL>>>(
            srcp, msrc, dstp, mdst,
            pimg + (size_t)i * 81920,
            out + (size_t)i * BATCH * 256 * SKIPLEN,
            1 << (i % 10));
    }
}